// round 7
// baseline (speedup 1.0000x reference)
#include <cuda_runtime.h>
#include <cuda_bf16.h>
#include <cuda_fp16.h>
#include <cstdint>

#define NN 50000
#define EE 600000
#define DD 128
#define LN_EPS 1e-5f

// ---------------- scratch (device globals: no runtime allocation) ----------------
__device__ float  g_buf0[NN * DD];   // agg/LN output (fp32, feeds next GEMM)
__device__ __half g_bufh[NN * DD];   // GEMM output messages (fp16)
__device__ int    g_deg[NN];
__device__ float  g_dinv[NN];
__device__ int    g_rowstart[NN + 1];
__device__ int    g_cursor[NN];
__device__ int    g_csr[EE];
__device__ int    g_partial[NN];
__device__ int    g_blocksums[64];
__device__ __nv_bfloat16 g_wh[3 * DD * DD];  // W^T hi, [l][n][k]
__device__ __nv_bfloat16 g_wl[3 * DD * DD];  // W^T lo, [l][n][k]

// ---------------- PTX helpers (generic sm_80+ ISA: ldmatrix + mma.sync) ----------------
__device__ __forceinline__ uint32_t smem_u32(const void* p) {
    uint32_t a;
    asm("{ .reg .u64 t; cvta.to.shared.u64 t, %1; cvt.u32.u64 %0, t; }" : "=r"(a) : "l"(p));
    return a;
}
__device__ __forceinline__ void ldsm_x4(uint32_t* r, uint32_t addr) {
    asm volatile("ldmatrix.sync.aligned.m8n8.x4.shared.b16 {%0,%1,%2,%3}, [%4];"
                 : "=r"(r[0]), "=r"(r[1]), "=r"(r[2]), "=r"(r[3]) : "r"(addr));
}
__device__ __forceinline__ void mma16816(float* c, const uint32_t* a, uint32_t b0, uint32_t b1) {
    asm volatile("mma.sync.aligned.m16n8k16.row.col.f32.bf16.bf16.f32 "
                 "{%0,%1,%2,%3}, {%4,%5,%6,%7}, {%8,%9}, {%0,%1,%2,%3};"
                 : "+f"(c[0]), "+f"(c[1]), "+f"(c[2]), "+f"(c[3])
                 : "r"(a[0]), "r"(a[1]), "r"(a[2]), "r"(a[3]), "r"(b0), "r"(b1));
}

// ---------------- preprocessing ----------------
__global__ void k_init_deg(int* deg) {
    int i = blockIdx.x * blockDim.x + threadIdx.x;
    if (i < NN) deg[i] = 1;
}
__global__ void k_hist(const int* __restrict__ dst, int* deg) {
    int e = blockIdx.x * blockDim.x + threadIdx.x;
    if (e < EE) atomicAdd(&deg[dst[e]], 1);
}
__global__ void k_scan_blocks(const int* __restrict__ deg, int* __restrict__ partial,
                              int* __restrict__ blocksums) {
    __shared__ int wsum[32];
    int gid = blockIdx.x * 1024 + threadIdx.x;
    int lane = threadIdx.x & 31, wid = threadIdx.x >> 5;
    int x = (gid < NN) ? (deg[gid] - 1) : 0;
    #pragma unroll
    for (int o = 1; o < 32; o <<= 1) {
        int y = __shfl_up_sync(0xFFFFFFFFu, x, o);
        if (lane >= o) x += y;
    }
    if (lane == 31) wsum[wid] = x;
    __syncthreads();
    if (wid == 0) {
        int s = wsum[lane];
        #pragma unroll
        for (int o = 1; o < 32; o <<= 1) {
            int y = __shfl_up_sync(0xFFFFFFFFu, s, o);
            if (lane >= o) s += y;
        }
        wsum[lane] = s;
    }
    __syncthreads();
    int incl = x + (wid > 0 ? wsum[wid - 1] : 0);
    if (gid < NN) partial[gid] = incl;
    if (threadIdx.x == 1023) blocksums[blockIdx.x] = incl;
}
__global__ void k_scan_sums(int* bs, int nb) {
    __shared__ int s[64];
    int t = threadIdx.x;
    s[t] = (t < nb) ? bs[t] : 0;
    __syncthreads();
    #pragma unroll
    for (int o = 1; o < 64; o <<= 1) {
        int x = (t >= o) ? s[t - o] : 0;
        __syncthreads();
        s[t] += x;
        __syncthreads();
    }
    if (t < nb) bs[t] = s[t];
}
__global__ void k_finalize(const int* __restrict__ partial, const int* __restrict__ blocksums,
                           const int* __restrict__ deg,
                           int* __restrict__ rowstart, int* __restrict__ cursor,
                           float* __restrict__ dinv) {
    int gid = blockIdx.x * blockDim.x + threadIdx.x;
    if (gid < NN) {
        int b = gid >> 10;
        int off = (b > 0) ? blocksums[b - 1] : 0;
        rowstart[gid + 1] = partial[gid] + off;
        cursor[gid] = 0;
        dinv[gid] = rsqrtf((float)deg[gid]);
        if (gid == 0) rowstart[0] = 0;
    }
}
__global__ void k_fill(const int* __restrict__ src, const int* __restrict__ dst,
                       const int* __restrict__ rowstart, int* __restrict__ cursor,
                       int* __restrict__ csr) {
    int e = blockIdx.x * blockDim.x + threadIdx.x;
    if (e < EE) {
        int d = dst[e];
        int p = atomicAdd(&cursor[d], 1);
        csr[rowstart[d] + p] = src[e];
    }
}

// ---------------- W convert+transpose (all 3 layers): wh/wl[l][n][k] = split(W[l][k][n]) ----------------
__global__ void k_convW(const float* __restrict__ W, __nv_bfloat16* __restrict__ wh,
                        __nv_bfloat16* __restrict__ wl) {
    int i = blockIdx.x * 256 + threadIdx.x;   // i = l*16384 + k*128 + c
    if (i < 3 * DD * DD) {
        int l = i >> 14;
        int r = i & (DD * DD - 1);
        int k = r >> 7, c = r & 127;
        float w = W[i];
        __nv_bfloat16 h = __float2bfloat16(w);
        float lo = w - __bfloat162float(h);
        wh[l * DD * DD + c * DD + k] = h;
        wl[l * DD * DD + c * DD + k] = __float2bfloat16(lo);
    }
}

// ---------------- HMMA GEMM: Ch[nrows x 128] = fp16(A @ W)  (split-bf16, f32 accum) ----------------
// CTA = 64 rows, 8 warps (2m x 4n), warp tile 32x32. 2 CTAs/SM.
#define PITCH 136
#define A_HW (64 * PITCH)                  // halfwords per A tile (64 rows)
#define W_HW (128 * PITCH)                 // halfwords per W tile
#define SM_AH 0
#define SM_AL (A_HW)
#define SM_WH (2 * A_HW)
#define SM_WL (2 * A_HW + W_HW)
#define SM_GEMM_BYTES ((2 * A_HW + 2 * W_HW) * 2)   // 104448

__global__ __launch_bounds__(256, 2) void k_gemm_mma(
    const float* __restrict__ A, const __nv_bfloat16* __restrict__ wh,
    const __nv_bfloat16* __restrict__ wl, __half* __restrict__ Ch, int nrows)
{
    extern __shared__ __nv_bfloat16 smem[];
    uint32_t sb = smem_u32(smem);
    int tid = threadIdx.x;
    int wid = tid >> 5, lane = tid & 31;

    // --- W tiles: [n][k] row-major -> padded SMEM ---
    {
        const uint32_t* wh32 = (const uint32_t*)wh;
        const uint32_t* wl32 = (const uint32_t*)wl;
        uint32_t* sWH = (uint32_t*)(smem + SM_WH);
        uint32_t* sWL = (uint32_t*)(smem + SM_WL);
        #pragma unroll
        for (int p = 0; p < 32; p++) {
            int idx = tid + p * 256;
            int n = idx >> 6, kp = idx & 63;
            int so = (n * PITCH) / 2 + kp;
            sWH[so] = wh32[idx];
            sWL[so] = wl32[idx];
        }
    }
    // --- A tile (64 rows), split hi/lo bf16: 4 threads per row, 32 cols each ---
    {
        int r  = tid >> 2;
        int k0 = (tid & 3) * 32;
        int gr = blockIdx.x * 64 + r;
        bool valid = (gr < nrows);
        const float4* arow = (const float4*)(A + (size_t)(valid ? gr : 0) * 128);
        uint32_t* sAH = (uint32_t*)(smem + SM_AH);
        uint32_t* sAL = (uint32_t*)(smem + SM_AL);
        #pragma unroll
        for (int k = 0; k < 32; k += 4) {
            float4 v = valid ? arow[(k0 + k) >> 2] : make_float4(0.f, 0.f, 0.f, 0.f);
            __nv_bfloat16 hx = __float2bfloat16(v.x), hy = __float2bfloat16(v.y);
            __nv_bfloat16 hz = __float2bfloat16(v.z), hw = __float2bfloat16(v.w);
            __nv_bfloat162 h01 = __halves2bfloat162(hx, hy);
            __nv_bfloat162 h23 = __halves2bfloat162(hz, hw);
            __nv_bfloat162 l01 = __halves2bfloat162(
                __float2bfloat16(v.x - __bfloat162float(hx)),
                __float2bfloat16(v.y - __bfloat162float(hy)));
            __nv_bfloat162 l23 = __halves2bfloat162(
                __float2bfloat16(v.z - __bfloat162float(hz)),
                __float2bfloat16(v.w - __bfloat162float(hw)));
            int so = (r * PITCH + k0 + k) / 2;
            sAH[so]     = *(uint32_t*)&h01;
            sAH[so + 1] = *(uint32_t*)&h23;
            sAL[so]     = *(uint32_t*)&l01;
            sAL[so + 1] = *(uint32_t*)&l23;
        }
    }
    __syncthreads();

    int warp_m = wid & 1;      // 0..1 -> rows warp_m*32
    int warp_n = wid >> 1;     // 0..3 -> cols warp_n*32
    float acc[2][4][4];
    #pragma unroll
    for (int mi = 0; mi < 2; mi++)
        #pragma unroll
        for (int ni = 0; ni < 4; ni++)
            #pragma unroll
            for (int j = 0; j < 4; j++) acc[mi][ni][j] = 0.f;

    int lrow = lane & 15;
    int lkof = (lane >> 4) * 8;

    #pragma unroll
    for (int pass = 0; pass < 3; pass++) {
        int aBase = (pass < 2) ? SM_AH : SM_AL;
        int bBase = (pass == 1) ? SM_WL : SM_WH;
        uint32_t aAddr = sb + (uint32_t)(aBase + (warp_m * 32 + lrow) * PITCH + lkof) * 2;
        uint32_t bAddr = sb + (uint32_t)(bBase + (warp_n * 32 + lrow) * PITCH + lkof) * 2;
        #pragma unroll
        for (int ks = 0; ks < 8; ks++) {
            uint32_t a0[4], a1[4];
            ldsm_x4(a0, aAddr + (uint32_t)(ks * 16) * 2);
            ldsm_x4(a1, aAddr + (uint32_t)(16 * PITCH + ks * 16) * 2);
            uint32_t b[2][4];
            ldsm_x4(b[0], bAddr + (uint32_t)(ks * 16) * 2);
            ldsm_x4(b[1], bAddr + (uint32_t)(16 * PITCH + ks * 16) * 2);
            #pragma unroll
            for (int nb = 0; nb < 2; nb++) {
                mma16816(acc[0][2 * nb],     a0, b[nb][0], b[nb][2]);
                mma16816(acc[0][2 * nb + 1], a0, b[nb][1], b[nb][3]);
                mma16816(acc[1][2 * nb],     a1, b[nb][0], b[nb][2]);
                mma16816(acc[1][2 * nb + 1], a1, b[nb][1], b[nb][3]);
            }
        }
    }

    // --- epilogue: write fp16 messages ---
    int qrow = lane >> 2;
    int qcol = (lane & 3) * 2;
    #pragma unroll
    for (int mi = 0; mi < 2; mi++) {
        int r0 = blockIdx.x * 64 + warp_m * 32 + mi * 16 + qrow;
        #pragma unroll
        for (int half = 0; half < 2; half++) {
            int gr = r0 + half * 8;
            if (gr < nrows) {
                __half* crow = Ch + (size_t)gr * 128 + warp_n * 32 + qcol;
                #pragma unroll
                for (int ni = 0; ni < 4; ni++) {
                    if (half) {
                        *(__half2*)(crow + ni * 8) =
                            __floats2half2_rn(acc[mi][ni][2], acc[mi][ni][3]);
                    } else {
                        *(__half2*)(crow + ni * 8) =
                            __floats2half2_rn(acc[mi][ni][0], acc[mi][ni][1]);
                    }
                }
            }
        }
    }
}

// ---------------- fused aggregation (fp16 msgs, fp32 accum) + bias + LN + PReLU ----------------
__global__ void k_agg_ln(const __half* __restrict__ t, float* __restrict__ out,
                         const int* __restrict__ rowstart, const int* __restrict__ csr,
                         const float* __restrict__ dinv,
                         const float* __restrict__ bias, const float* __restrict__ lnw,
                         const float* __restrict__ lnb, const float* __restrict__ alpha_p) {
    int w = (blockIdx.x * blockDim.x + threadIdx.x) >> 5;
    if (w >= NN) return;
    int lane = threadIdx.x & 31;
    const uint2* t2 = (const uint2*)t;   // 4 halfs per uint2; 32 per row
    float di = dinv[w];
    uint2 raw = t2[(size_t)w * 32 + lane];
    float2 f0 = __half22float2(*(__half2*)&raw.x);
    float2 f1 = __half22float2(*(__half2*)&raw.y);
    float s2 = di * di;
    float4 acc = make_float4(f0.x * s2, f0.y * s2, f1.x * s2, f1.y * s2);
    int e = rowstart[w], e1 = rowstart[w + 1];
    for (; e + 1 < e1; e += 2) {
        int sA = csr[e], sB = csr[e + 1];
        float wA = dinv[sA] * di, wB = dinv[sB] * di;
        uint2 rA = t2[(size_t)sA * 32 + lane];
        uint2 rB = t2[(size_t)sB * 32 + lane];
        float2 a0 = __half22float2(*(__half2*)&rA.x);
        float2 a1 = __half22float2(*(__half2*)&rA.y);
        float2 b0 = __half22float2(*(__half2*)&rB.x);
        float2 b1 = __half22float2(*(__half2*)&rB.y);
        acc.x += wA * a0.x + wB * b0.x;
        acc.y += wA * a0.y + wB * b0.y;
        acc.z += wA * a1.x + wB * b1.x;
        acc.w += wA * a1.y + wB * b1.y;
    }
    if (e < e1) {
        int sA = csr[e];
        float wA = dinv[sA] * di;
        uint2 rA = t2[(size_t)sA * 32 + lane];
        float2 a0 = __half22float2(*(__half2*)&rA.x);
        float2 a1 = __half22float2(*(__half2*)&rA.y);
        acc.x += wA * a0.x; acc.y += wA * a0.y;
        acc.z += wA * a1.x; acc.w += wA * a1.y;
    }
    // bias + LN + PReLU
    float4 b = ((const float4*)bias)[lane];
    acc.x += b.x; acc.y += b.y; acc.z += b.z; acc.w += b.w;
    float s = acc.x + acc.y + acc.z + acc.w;
    #pragma unroll
    for (int o = 16; o > 0; o >>= 1) s += __shfl_xor_sync(0xFFFFFFFFu, s, o);
    float mean = s * (1.f / 128.f);
    float dx = acc.x - mean, dy = acc.y - mean, dz = acc.z - mean, dw = acc.w - mean;
    float q = dx * dx + dy * dy + dz * dz + dw * dw;
    #pragma unroll
    for (int o = 16; o > 0; o >>= 1) q += __shfl_xor_sync(0xFFFFFFFFu, q, o);
    float rstd = rsqrtf(q * (1.f / 128.f) + LN_EPS);
    float4 gw = ((const float4*)lnw)[lane];
    float4 gb = ((const float4*)lnb)[lane];
    float a = alpha_p[0];
    float4 y;
    y.x = dx * rstd * gw.x + gb.x; y.x = y.x >= 0.f ? y.x : a * y.x;
    y.y = dy * rstd * gw.y + gb.y; y.y = y.y >= 0.f ? y.y : a * y.y;
    y.z = dz * rstd * gw.z + gb.z; y.z = y.z >= 0.f ? y.z : a * y.z;
    y.w = dw * rstd * gw.w + gb.w; y.w = y.w >= 0.f ? y.w : a * y.w;
    ((float4*)out)[w * 32 + lane] = y;
}

// ---------------- launch ----------------
extern "C" void kernel_launch(void* const* d_in, const int* in_sizes, int n_in,
                              void* d_out, int out_size) {
    const float* x      = (const float*)d_in[0];
    const int*   ei     = (const int*)d_in[1];
    const float* Ws     = (const float*)d_in[2];
    const float* bs     = (const float*)d_in[3];
    const float* lnw    = (const float*)d_in[4];
    const float* lnb    = (const float*)d_in[5];
    const float* alphas = (const float*)d_in[6];
    float* out = (float*)d_out;
    const int* src = ei;
    const int* dst = ei + EE;

    float *buf0, *dinv;
    __half* bufh;
    int *deg, *rowstart, *cursor, *csr, *partial, *blocksums;
    __nv_bfloat16 *wh, *wl;
    cudaGetSymbolAddress((void**)&buf0, g_buf0);
    cudaGetSymbolAddress((void**)&bufh, g_bufh);
    cudaGetSymbolAddress((void**)&deg, g_deg);
    cudaGetSymbolAddress((void**)&dinv, g_dinv);
    cudaGetSymbolAddress((void**)&rowstart, g_rowstart);
    cudaGetSymbolAddress((void**)&cursor, g_cursor);
    cudaGetSymbolAddress((void**)&csr, g_csr);
    cudaGetSymbolAddress((void**)&partial, g_partial);
    cudaGetSymbolAddress((void**)&blocksums, g_blocksums);
    cudaGetSymbolAddress((void**)&wh, g_wh);
    cudaGetSymbolAddress((void**)&wl, g_wl);

    cudaFuncSetAttribute(k_gemm_mma, cudaFuncAttributeMaxDynamicSharedMemorySize, SM_GEMM_BYTES);

    const int nbN   = (NN + 255) / 256;
    const int nbE   = (EE + 255) / 256;
    const int nbSc  = (NN + 1023) / 1024;
    const int nbRow = (NN * 32 + 255) / 256;
    const int nbG   = (NN + 63) / 64;        // 782

    // gemm0 at launch slot 4 (ncu profiles that slot)
    k_init_deg<<<nbN, 256>>>(deg);                                        // 1
    k_hist<<<nbE, 256>>>(dst, deg);                                       // 2
    k_convW<<<(3 * DD * DD + 255) / 256, 256>>>(Ws, wh, wl);              // 3
    k_gemm_mma<<<nbG, 256, SM_GEMM_BYTES>>>(x, wh, wl, bufh, NN);         // 4 (layer 0 GEMM)
    k_scan_blocks<<<nbSc, 1024>>>(deg, partial, blocksums);               // 5
    k_scan_sums<<<1, 64>>>(blocksums, nbSc);                              // 6
    k_finalize<<<nbN, 256>>>(partial, blocksums, deg, rowstart, cursor, dinv); // 7
    k_fill<<<nbE, 256>>>(src, dst, rowstart, cursor, csr);                // 8

    // layer 0 aggregation
    k_agg_ln<<<nbRow, 256>>>(bufh, buf0, rowstart, csr, dinv,
                             bs + 0 * DD, lnw + 0 * DD, lnb + 0 * DD, alphas + 0);
    // layer 1
    k_gemm_mma<<<nbG, 256, SM_GEMM_BYTES>>>(buf0, wh + 1 * DD * DD, wl + 1 * DD * DD, bufh, NN);
    k_agg_ln<<<nbRow, 256>>>(bufh, buf0, rowstart, csr, dinv,
                             bs + 1 * DD, lnw + 1 * DD, lnb + 1 * DD, alphas + 1);
    // layer 2 (final output fp32)
    k_gemm_mma<<<nbG, 256, SM_GEMM_BYTES>>>(buf0, wh + 2 * DD * DD, wl + 2 * DD * DD, bufh, NN);
    k_agg_ln<<<nbRow, 256>>>(bufh, out, rowstart, csr, dinv,
                             bs + 2 * DD, lnw + 2 * DD, lnb + 2 * DD, alphas + 2);
}

// round 8
// speedup vs baseline: 1.0997x; 1.0997x over previous
#include <cuda_runtime.h>
#include <cuda_bf16.h>
#include <cuda_fp16.h>
#include <cstdint>

#define NN 50000
#define EE 600000
#define DD 128
#define LN_EPS 1e-5f

// ---------------- scratch (device globals: no runtime allocation) ----------------
__device__ __nv_bfloat16 g_ah[NN * DD];  // activation hi (GEMM input)
__device__ __nv_bfloat16 g_al[NN * DD];  // activation lo
__device__ __half        g_bufh[NN * DD]; // GEMM output messages (fp16)
__device__ int    g_deg[NN];
__device__ float  g_dinv[NN];
__device__ int    g_rowstart[NN + 1];
__device__ int    g_cursor[NN];
__device__ int    g_csr[EE];
__device__ int    g_partial[NN];
__device__ int    g_blocksums[64];
__device__ __nv_bfloat16 g_wh[3 * DD * DD];  // W^T hi, [l][n][k]
__device__ __nv_bfloat16 g_wl[3 * DD * DD];  // W^T lo, [l][n][k]

// ---------------- PTX helpers ----------------
__device__ __forceinline__ uint32_t smem_u32(const void* p) {
    uint32_t a;
    asm("{ .reg .u64 t; cvta.to.shared.u64 t, %1; cvt.u32.u64 %0, t; }" : "=r"(a) : "l"(p));
    return a;
}
__device__ __forceinline__ void ldsm_x4(uint32_t* r, uint32_t addr) {
    asm volatile("ldmatrix.sync.aligned.m8n8.x4.shared.b16 {%0,%1,%2,%3}, [%4];"
                 : "=r"(r[0]), "=r"(r[1]), "=r"(r[2]), "=r"(r[3]) : "r"(addr));
}
__device__ __forceinline__ void mma16816(float* c, const uint32_t* a, uint32_t b0, uint32_t b1) {
    asm volatile("mma.sync.aligned.m16n8k16.row.col.f32.bf16.bf16.f32 "
                 "{%0,%1,%2,%3}, {%4,%5,%6,%7}, {%8,%9}, {%0,%1,%2,%3};"
                 : "+f"(c[0]), "+f"(c[1]), "+f"(c[2]), "+f"(c[3])
                 : "r"(a[0]), "r"(a[1]), "r"(a[2]), "r"(a[3]), "r"(b0), "r"(b1));
}
__device__ __forceinline__ void cp_async16(uint32_t saddr, const void* gaddr) {
    asm volatile("cp.async.cg.shared.global [%0], [%1], 16;" :: "r"(saddr), "l"(gaddr));
}
#define CP_COMMIT() asm volatile("cp.async.commit_group;" ::: "memory")
#define CP_WAIT0()  asm volatile("cp.async.wait_group 0;" ::: "memory")

// ---------------- preprocessing ----------------
__global__ void k_init_deg(int* deg) {
    int i = blockIdx.x * blockDim.x + threadIdx.x;
    if (i < NN) deg[i] = 1;
}
__global__ void k_hist(const int* __restrict__ dst, int* deg) {
    int e = blockIdx.x * blockDim.x + threadIdx.x;
    if (e < EE) atomicAdd(&deg[dst[e]], 1);
}
__global__ void k_scan_blocks(const int* __restrict__ deg, int* __restrict__ partial,
                              int* __restrict__ blocksums) {
    __shared__ int wsum[32];
    int gid = blockIdx.x * 1024 + threadIdx.x;
    int lane = threadIdx.x & 31, wid = threadIdx.x >> 5;
    int x = (gid < NN) ? (deg[gid] - 1) : 0;
    #pragma unroll
    for (int o = 1; o < 32; o <<= 1) {
        int y = __shfl_up_sync(0xFFFFFFFFu, x, o);
        if (lane >= o) x += y;
    }
    if (lane == 31) wsum[wid] = x;
    __syncthreads();
    if (wid == 0) {
        int s = wsum[lane];
        #pragma unroll
        for (int o = 1; o < 32; o <<= 1) {
            int y = __shfl_up_sync(0xFFFFFFFFu, s, o);
            if (lane >= o) s += y;
        }
        wsum[lane] = s;
    }
    __syncthreads();
    int incl = x + (wid > 0 ? wsum[wid - 1] : 0);
    if (gid < NN) partial[gid] = incl;
    if (threadIdx.x == 1023) blocksums[blockIdx.x] = incl;
}
__global__ void k_scan_sums(int* bs, int nb) {
    __shared__ int s[64];
    int t = threadIdx.x;
    s[t] = (t < nb) ? bs[t] : 0;
    __syncthreads();
    #pragma unroll
    for (int o = 1; o < 64; o <<= 1) {
        int x = (t >= o) ? s[t - o] : 0;
        __syncthreads();
        s[t] += x;
        __syncthreads();
    }
    if (t < nb) bs[t] = s[t];
}
__global__ void k_finalize(const int* __restrict__ partial, const int* __restrict__ blocksums,
                           const int* __restrict__ deg,
                           int* __restrict__ rowstart, int* __restrict__ cursor,
                           float* __restrict__ dinv) {
    int gid = blockIdx.x * blockDim.x + threadIdx.x;
    if (gid < NN) {
        int b = gid >> 10;
        int off = (b > 0) ? blocksums[b - 1] : 0;
        rowstart[gid + 1] = partial[gid] + off;
        cursor[gid] = 0;
        dinv[gid] = rsqrtf((float)deg[gid]);
        if (gid == 0) rowstart[0] = 0;
    }
}
__global__ void k_fill(const int* __restrict__ src, const int* __restrict__ dst,
                       const int* __restrict__ rowstart, int* __restrict__ cursor,
                       int* __restrict__ csr) {
    int e = blockIdx.x * blockDim.x + threadIdx.x;
    if (e < EE) {
        int d = dst[e];
        int p = atomicAdd(&cursor[d], 1);
        csr[rowstart[d] + p] = src[e];
    }
}

// ---------------- W convert+transpose (all 3 layers): wh/wl[l][n][k] = split(W[l][k][n]) ----------------
__global__ void k_convW(const float* __restrict__ W, __nv_bfloat16* __restrict__ wh,
                        __nv_bfloat16* __restrict__ wl) {
    int i = blockIdx.x * 256 + threadIdx.x;
    if (i < 3 * DD * DD) {
        int l = i >> 14;
        int r = i & (DD * DD - 1);
        int k = r >> 7, c = r & 127;
        float w = W[i];
        __nv_bfloat16 h = __float2bfloat16(w);
        float lo = w - __bfloat162float(h);
        wh[l * DD * DD + c * DD + k] = h;
        wl[l * DD * DD + c * DD + k] = __float2bfloat16(lo);
    }
}

// ---------------- split x (layer-0 input) into bf16 hi/lo ----------------
__global__ void k_splitX(const float* __restrict__ x, __nv_bfloat16* __restrict__ xh,
                         __nv_bfloat16* __restrict__ xl) {
    int i = blockIdx.x * 256 + threadIdx.x;   // float4 index
    if (i < NN * 32) {
        float4 v = ((const float4*)x)[i];
        __nv_bfloat16 hx = __float2bfloat16(v.x), hy = __float2bfloat16(v.y);
        __nv_bfloat16 hz = __float2bfloat16(v.z), hw = __float2bfloat16(v.w);
        __nv_bfloat162 h01 = __halves2bfloat162(hx, hy);
        __nv_bfloat162 h23 = __halves2bfloat162(hz, hw);
        __nv_bfloat162 l01 = __halves2bfloat162(
            __float2bfloat16(v.x - __bfloat162float(hx)),
            __float2bfloat16(v.y - __bfloat162float(hy)));
        __nv_bfloat162 l23 = __halves2bfloat162(
            __float2bfloat16(v.z - __bfloat162float(hz)),
            __float2bfloat16(v.w - __bfloat162float(hw)));
        ((uint32_t*)xh)[i * 2]     = *(uint32_t*)&h01;
        ((uint32_t*)xh)[i * 2 + 1] = *(uint32_t*)&h23;
        ((uint32_t*)xl)[i * 2]     = *(uint32_t*)&l01;
        ((uint32_t*)xl)[i * 2 + 1] = *(uint32_t*)&l23;
    }
}

// ---------------- HMMA GEMM: Ch[nrows x 128] = fp16(A @ W) ----------------
// CTA = 128 rows, K split into 2 chunks of 64. smem per chunk set = 72 KB -> 2 CTAs/SM.
// Warp tiling 4m x 2n (warp tile 32 x 64), same as R6 winner.
#define CH_PITCH 72
#define CH_TILE_B (128 * CH_PITCH * 2)     // bytes per chunk tile = 18432
#define SM_AH_B 0
#define SM_AL_B (CH_TILE_B)
#define SM_WH_B (2 * CH_TILE_B)
#define SM_WL_B (3 * CH_TILE_B)
#define SM_GEMM_BYTES (4 * CH_TILE_B)      // 73728

__global__ __launch_bounds__(256, 2) void k_gemm_mma(
    const __nv_bfloat16* __restrict__ ah, const __nv_bfloat16* __restrict__ al,
    const __nv_bfloat16* __restrict__ wh, const __nv_bfloat16* __restrict__ wl,
    __half* __restrict__ Ch, int nrows)
{
    extern __shared__ __nv_bfloat16 smem[];
    uint32_t sb = smem_u32(smem);
    int tid = threadIdx.x;
    int wid = tid >> 5, lane = tid & 31;

    int warp_m = wid & 3;      // rows warp_m*32
    int warp_n = wid >> 2;     // cols warp_n*64
    float acc[2][8][4];
    #pragma unroll
    for (int mi = 0; mi < 2; mi++)
        #pragma unroll
        for (int ni = 0; ni < 8; ni++)
            #pragma unroll
            for (int j = 0; j < 4; j++) acc[mi][ni][j] = 0.f;

    int lrow = lane & 15;
    int lkof = (lane >> 4) * 8;
    int r0f = tid >> 3;        // fill row base 0..31
    int jf  = tid & 7;         // 16B chunk within 128B row segment
    int gblk = blockIdx.x * 128;

    #pragma unroll
    for (int chunk = 0; chunk < 2; chunk++) {
        // ---- fill chunk via cp.async (A hi/lo + W hi/lo, rows x 64 k) ----
        if (chunk) __syncthreads();   // protect smem reuse
        #pragma unroll
        for (int q = 0; q < 4; q++) {
            int r = r0f + q * 32;
            uint32_t sa = sb + (uint32_t)(r * CH_PITCH * 2 + jf * 16);
            size_t go = (size_t)r * 128 + chunk * 64 + jf * 8;
            if (gblk + r < nrows) {
                size_t ga = (size_t)gblk * 128 + go;
                cp_async16(sa + SM_AH_B, ah + ga);
                cp_async16(sa + SM_AL_B, al + ga);
            }
            cp_async16(sa + SM_WH_B, wh + go);
            cp_async16(sa + SM_WL_B, wl + go);
        }
        CP_COMMIT();
        CP_WAIT0();
        __syncthreads();

        // ---- 3 passes x 4 k-steps ----
        #pragma unroll
        for (int pass = 0; pass < 3; pass++) {
            uint32_t aBase = (pass < 2) ? SM_AH_B : SM_AL_B;
            uint32_t bBase = (pass == 1) ? SM_WL_B : SM_WH_B;
            uint32_t aAddr = sb + aBase + (uint32_t)(((warp_m * 32 + lrow) * CH_PITCH + lkof) * 2);
            uint32_t bAddr = sb + bBase + (uint32_t)(((warp_n * 64 + lrow) * CH_PITCH + lkof) * 2);
            #pragma unroll
            for (int ks = 0; ks < 4; ks++) {
                uint32_t a0[4], a1[4];
                ldsm_x4(a0, aAddr + (uint32_t)(ks * 32));
                ldsm_x4(a1, aAddr + (uint32_t)(16 * CH_PITCH * 2 + ks * 32));
                uint32_t b[4][4];
                #pragma unroll
                for (int nb = 0; nb < 4; nb++)
                    ldsm_x4(b[nb], bAddr + (uint32_t)(nb * 16 * CH_PITCH * 2 + ks * 32));
                #pragma unroll
                for (int nb = 0; nb < 4; nb++) {
                    mma16816(acc[0][2 * nb],     a0, b[nb][0], b[nb][2]);
                    mma16816(acc[0][2 * nb + 1], a0, b[nb][1], b[nb][3]);
                    mma16816(acc[1][2 * nb],     a1, b[nb][0], b[nb][2]);
                    mma16816(acc[1][2 * nb + 1], a1, b[nb][1], b[nb][3]);
                }
            }
        }
    }

    // ---- epilogue: write fp16 messages ----
    int qrow = lane >> 2;
    int qcol = (lane & 3) * 2;
    #pragma unroll
    for (int mi = 0; mi < 2; mi++) {
        int r0 = gblk + warp_m * 32 + mi * 16 + qrow;
        #pragma unroll
        for (int half = 0; half < 2; half++) {
            int gr = r0 + half * 8;
            if (gr < nrows) {
                __half* crow = Ch + (size_t)gr * 128 + warp_n * 64 + qcol;
                #pragma unroll
                for (int ni = 0; ni < 8; ni++) {
                    if (half) {
                        *(__half2*)(crow + ni * 8) =
                            __floats2half2_rn(acc[mi][ni][2], acc[mi][ni][3]);
                    } else {
                        *(__half2*)(crow + ni * 8) =
                            __floats2half2_rn(acc[mi][ni][0], acc[mi][ni][1]);
                    }
                }
            }
        }
    }
}

// ---------------- fused aggregation (fp16 msgs, fp32 accum) + bias + LN + PReLU ----------------
// last==0: write split-bf16 activation (oh/ol). last==1: write fp32 out.
__global__ void k_agg_ln(const __half* __restrict__ t,
                         __nv_bfloat16* __restrict__ oh, __nv_bfloat16* __restrict__ ol,
                         float* __restrict__ out32, int last,
                         const int* __restrict__ rowstart, const int* __restrict__ csr,
                         const float* __restrict__ dinv,
                         const float* __restrict__ bias, const float* __restrict__ lnw,
                         const float* __restrict__ lnb, const float* __restrict__ alpha_p) {
    int w = (blockIdx.x * blockDim.x + threadIdx.x) >> 5;
    if (w >= NN) return;
    int lane = threadIdx.x & 31;
    const uint2* t2 = (const uint2*)t;
    float di = dinv[w];
    uint2 raw = t2[(size_t)w * 32 + lane];
    float2 f0 = __half22float2(*(__half2*)&raw.x);
    float2 f1 = __half22float2(*(__half2*)&raw.y);
    float s2 = di * di;
    float4 acc = make_float4(f0.x * s2, f0.y * s2, f1.x * s2, f1.y * s2);
    int e = rowstart[w], e1 = rowstart[w + 1];
    for (; e + 1 < e1; e += 2) {
        int sA = csr[e], sB = csr[e + 1];
        float wA = dinv[sA] * di, wB = dinv[sB] * di;
        uint2 rA = t2[(size_t)sA * 32 + lane];
        uint2 rB = t2[(size_t)sB * 32 + lane];
        float2 a0 = __half22float2(*(__half2*)&rA.x);
        float2 a1 = __half22float2(*(__half2*)&rA.y);
        float2 b0 = __half22float2(*(__half2*)&rB.x);
        float2 b1 = __half22float2(*(__half2*)&rB.y);
        acc.x += wA * a0.x + wB * b0.x;
        acc.y += wA * a0.y + wB * b0.y;
        acc.z += wA * a1.x + wB * b1.x;
        acc.w += wA * a1.y + wB * b1.y;
    }
    if (e < e1) {
        int sA = csr[e];
        float wA = dinv[sA] * di;
        uint2 rA = t2[(size_t)sA * 32 + lane];
        float2 a0 = __half22float2(*(__half2*)&rA.x);
        float2 a1 = __half22float2(*(__half2*)&rA.y);
        acc.x += wA * a0.x; acc.y += wA * a0.y;
        acc.z += wA * a1.x; acc.w += wA * a1.y;
    }
    float4 b = ((const float4*)bias)[lane];
    acc.x += b.x; acc.y += b.y; acc.z += b.z; acc.w += b.w;
    float s = acc.x + acc.y + acc.z + acc.w;
    #pragma unroll
    for (int o = 16; o > 0; o >>= 1) s += __shfl_xor_sync(0xFFFFFFFFu, s, o);
    float mean = s * (1.f / 128.f);
    float dx = acc.x - mean, dy = acc.y - mean, dz = acc.z - mean, dw = acc.w - mean;
    float q = dx * dx + dy * dy + dz * dz + dw * dw;
    #pragma unroll
    for (int o = 16; o > 0; o >>= 1) q += __shfl_xor_sync(0xFFFFFFFFu, q, o);
    float rstd = rsqrtf(q * (1.f / 128.f) + LN_EPS);
    float4 gw = ((const float4*)lnw)[lane];
    float4 gb = ((const float4*)lnb)[lane];
    float a = alpha_p[0];
    float4 y;
    y.x = dx * rstd * gw.x + gb.x; y.x = y.x >= 0.f ? y.x : a * y.x;
    y.y = dy * rstd * gw.y + gb.y; y.y = y.y >= 0.f ? y.y : a * y.y;
    y.z = dz * rstd * gw.z + gb.z; y.z = y.z >= 0.f ? y.z : a * y.z;
    y.w = dw * rstd * gw.w + gb.w; y.w = y.w >= 0.f ? y.w : a * y.w;
    if (last) {
        ((float4*)out32)[(size_t)w * 32 + lane] = y;
    } else {
        __nv_bfloat16 hx = __float2bfloat16(y.x), hy = __float2bfloat16(y.y);
        __nv_bfloat16 hz = __float2bfloat16(y.z), hw = __float2bfloat16(y.w);
        __nv_bfloat162 h01 = __halves2bfloat162(hx, hy);
        __nv_bfloat162 h23 = __halves2bfloat162(hz, hw);
        __nv_bfloat162 l01 = __halves2bfloat162(
            __float2bfloat16(y.x - __bfloat162float(hx)),
            __float2bfloat16(y.y - __bfloat162float(hy)));
        __nv_bfloat162 l23 = __halves2bfloat162(
            __float2bfloat16(y.z - __bfloat162float(hz)),
            __float2bfloat16(y.w - __bfloat162float(hw)));
        uint32_t* po = (uint32_t*)oh + (size_t)w * 64 + lane * 2;
        uint32_t* pl = (uint32_t*)ol + (size_t)w * 64 + lane * 2;
        po[0] = *(uint32_t*)&h01; po[1] = *(uint32_t*)&h23;
        pl[0] = *(uint32_t*)&l01; pl[1] = *(uint32_t*)&l23;
    }
}

// ---------------- launch ----------------
extern "C" void kernel_launch(void* const* d_in, const int* in_sizes, int n_in,
                              void* d_out, int out_size) {
    const float* x      = (const float*)d_in[0];
    const int*   ei     = (const int*)d_in[1];
    const float* Ws     = (const float*)d_in[2];
    const float* bs     = (const float*)d_in[3];
    const float* lnw    = (const float*)d_in[4];
    const float* lnb    = (const float*)d_in[5];
    const float* alphas = (const float*)d_in[6];
    float* out = (float*)d_out;
    const int* src = ei;
    const int* dst = ei + EE;

    float* dinv;
    __half* bufh;
    __nv_bfloat16 *ah, *al, *wh, *wl;
    int *deg, *rowstart, *cursor, *csr, *partial, *blocksums;
    cudaGetSymbolAddress((void**)&ah, g_ah);
    cudaGetSymbolAddress((void**)&al, g_al);
    cudaGetSymbolAddress((void**)&bufh, g_bufh);
    cudaGetSymbolAddress((void**)&deg, g_deg);
    cudaGetSymbolAddress((void**)&dinv, g_dinv);
    cudaGetSymbolAddress((void**)&rowstart, g_rowstart);
    cudaGetSymbolAddress((void**)&cursor, g_cursor);
    cudaGetSymbolAddress((void**)&csr, g_csr);
    cudaGetSymbolAddress((void**)&partial, g_partial);
    cudaGetSymbolAddress((void**)&blocksums, g_blocksums);
    cudaGetSymbolAddress((void**)&wh, g_wh);
    cudaGetSymbolAddress((void**)&wl, g_wl);

    cudaFuncSetAttribute(k_gemm_mma, cudaFuncAttributeMaxDynamicSharedMemorySize, SM_GEMM_BYTES);

    const int nbN   = (NN + 255) / 256;
    const int nbE   = (EE + 255) / 256;
    const int nbSc  = (NN + 1023) / 1024;
    const int nbRow = (NN * 32 + 255) / 256;
    const int nbG   = (NN + 127) / 128;      // 391

    // gemm layer0 at launch slot 4 (ncu profiles that slot)
    k_init_deg<<<nbN, 256>>>(deg);                                        // 1
    k_convW<<<(3 * DD * DD + 255) / 256, 256>>>(Ws, wh, wl);              // 2
    k_splitX<<<(NN * 32 + 255) / 256, 256>>>(x, ah, al);                  // 3
    k_gemm_mma<<<nbG, 256, SM_GEMM_BYTES>>>(ah, al, wh, wl, bufh, NN);    // 4 (layer 0 GEMM)
    k_hist<<<nbE, 256>>>(dst, deg);                                       // 5
    k_scan_blocks<<<nbSc, 1024>>>(deg, partial, blocksums);               // 6
    k_scan_sums<<<1, 64>>>(blocksums, nbSc);                              // 7
    k_finalize<<<nbN, 256>>>(partial, blocksums, deg, rowstart, cursor, dinv); // 8
    k_fill<<<nbE, 256>>>(src, dst, rowstart, cursor, csr);                // 9

    // layer 0 aggregation -> split-bf16 activations
    k_agg_ln<<<nbRow, 256>>>(bufh, ah, al, nullptr, 0, rowstart, csr, dinv,
                             bs + 0 * DD, lnw + 0 * DD, lnb + 0 * DD, alphas + 0);
    // layer 1
    k_gemm_mma<<<nbG, 256, SM_GEMM_BYTES>>>(ah, al, wh + 1 * DD * DD, wl + 1 * DD * DD, bufh, NN);
    k_agg_ln<<<nbRow, 256>>>(bufh, ah, al, nullptr, 0, rowstart, csr, dinv,
                             bs + 1 * DD, lnw + 1 * DD, lnb + 1 * DD, alphas + 1);
    // layer 2 (final output fp32)
    k_gemm_mma<<<nbG, 256, SM_GEMM_BYTES>>>(ah, al, wh + 2 * DD * DD, wl + 2 * DD * DD, bufh, NN);
    k_agg_ln<<<nbRow, 256>>>(bufh, nullptr, nullptr, out, 1, rowstart, csr, dinv,
                             bs + 2 * DD, lnw + 2 * DD, lnb + 2 * DD, alphas + 2);
}

// round 10
// speedup vs baseline: 1.3904x; 1.2644x over previous
#include <cuda_runtime.h>
#include <cuda_bf16.h>
#include <cuda_fp16.h>
#include <cstdint>

#define NN 50000
#define EE 600000
#define DD 128
#define LN_EPS 1e-5f

// ---------------- scratch (device globals: no runtime allocation) ----------------
__device__ __half g_act[NN * DD];    // GEMM input activations (fp16)
__device__ __half g_bufh[NN * DD];   // GEMM output messages (fp16)
__device__ int    g_deg[NN];
__device__ float  g_dinv[NN];
__device__ int    g_rowstart[NN + 1];
__device__ int    g_cursor[NN];
__device__ int    g_csr[EE];
__device__ int    g_partial[NN];
__device__ int    g_blocksums[64];
__device__ __half g_w16[3 * DD * DD]; // W^T fp16, [l][n][k]

// ---------------- PTX helpers ----------------
__device__ __forceinline__ uint32_t smem_u32(const void* p) {
    uint32_t a;
    asm("{ .reg .u64 t; cvta.to.shared.u64 t, %1; cvt.u32.u64 %0, t; }" : "=r"(a) : "l"(p));
    return a;
}
__device__ __forceinline__ void ldsm_x4(uint32_t* r, uint32_t addr) {
    asm volatile("ldmatrix.sync.aligned.m8n8.x4.shared.b16 {%0,%1,%2,%3}, [%4];"
                 : "=r"(r[0]), "=r"(r[1]), "=r"(r[2]), "=r"(r[3]) : "r"(addr));
}
__device__ __forceinline__ void mma16816h(float* c, const uint32_t* a, uint32_t b0, uint32_t b1) {
    asm volatile("mma.sync.aligned.m16n8k16.row.col.f32.f16.f16.f32 "
                 "{%0,%1,%2,%3}, {%4,%5,%6,%7}, {%8,%9}, {%0,%1,%2,%3};"
                 : "+f"(c[0]), "+f"(c[1]), "+f"(c[2]), "+f"(c[3])
                 : "r"(a[0]), "r"(a[1]), "r"(a[2]), "r"(a[3]), "r"(b0), "r"(b1));
}
__device__ __forceinline__ void cp_async16(uint32_t saddr, const void* gaddr) {
    asm volatile("cp.async.cg.shared.global [%0], [%1], 16;" :: "r"(saddr), "l"(gaddr));
}
#define CP_COMMIT() asm volatile("cp.async.commit_group;" ::: "memory")
#define CP_WAIT0()  asm volatile("cp.async.wait_group 0;" ::: "memory")

// ---------------- preprocessing ----------------
__global__ void k_init_deg(int* deg) {
    int i = blockIdx.x * blockDim.x + threadIdx.x;
    if (i < NN) deg[i] = 1;
}
__global__ void k_hist(const int* __restrict__ dst, int* deg) {
    int e = blockIdx.x * blockDim.x + threadIdx.x;
    if (e < EE) atomicAdd(&deg[dst[e]], 1);
}
__global__ void k_scan_blocks(const int* __restrict__ deg, int* __restrict__ partial,
                              int* __restrict__ blocksums) {
    __shared__ int wsum[32];
    int gid = blockIdx.x * 1024 + threadIdx.x;
    int lane = threadIdx.x & 31, wid = threadIdx.x >> 5;
    int x = (gid < NN) ? (deg[gid] - 1) : 0;
    #pragma unroll
    for (int o = 1; o < 32; o <<= 1) {
        int y = __shfl_up_sync(0xFFFFFFFFu, x, o);
        if (lane >= o) x += y;
    }
    if (lane == 31) wsum[wid] = x;
    __syncthreads();
    if (wid == 0) {
        int s = wsum[lane];
        #pragma unroll
        for (int o = 1; o < 32; o <<= 1) {
            int y = __shfl_up_sync(0xFFFFFFFFu, s, o);
            if (lane >= o) s += y;
        }
        wsum[lane] = s;
    }
    __syncthreads();
    int incl = x + (wid > 0 ? wsum[wid - 1] : 0);
    if (gid < NN) partial[gid] = incl;
    if (threadIdx.x == 1023) blocksums[blockIdx.x] = incl;
}
__global__ void k_scan_sums(int* bs, int nb) {
    __shared__ int s[64];
    int t = threadIdx.x;
    s[t] = (t < nb) ? bs[t] : 0;
    __syncthreads();
    #pragma unroll
    for (int o = 1; o < 64; o <<= 1) {
        int x = (t >= o) ? s[t - o] : 0;
        __syncthreads();
        s[t] += x;
        __syncthreads();
    }
    if (t < nb) bs[t] = s[t];
}
__global__ void k_finalize(const int* __restrict__ partial, const int* __restrict__ blocksums,
                           const int* __restrict__ deg,
                           int* __restrict__ rowstart, int* __restrict__ cursor,
                           float* __restrict__ dinv) {
    int gid = blockIdx.x * blockDim.x + threadIdx.x;
    if (gid < NN) {
        int b = gid >> 10;
        int off = (b > 0) ? blocksums[b - 1] : 0;
        rowstart[gid + 1] = partial[gid] + off;
        cursor[gid] = 0;
        dinv[gid] = rsqrtf((float)deg[gid]);
        if (gid == 0) rowstart[0] = 0;
    }
}
__global__ void k_fill(const int* __restrict__ src, const int* __restrict__ dst,
                       const int* __restrict__ rowstart, int* __restrict__ cursor,
                       int* __restrict__ csr) {
    int e = blockIdx.x * blockDim.x + threadIdx.x;
    if (e < EE) {
        int d = dst[e];
        int p = atomicAdd(&cursor[d], 1);
        csr[rowstart[d] + p] = src[e];
    }
}

// ---------------- W convert+transpose (all 3 layers): w16[l][n][k] = fp16(W[l][k][n]) ----------------
__global__ void k_convW(const float* __restrict__ W, __half* __restrict__ w16) {
    int i = blockIdx.x * 256 + threadIdx.x;
    if (i < 3 * DD * DD) {
        int l = i >> 14;
        int r = i & (DD * DD - 1);
        int k = r >> 7, c = r & 127;
        w16[l * DD * DD + c * DD + k] = __float2half(W[i]);
    }
}

// ---------------- convert x (layer-0 input) to fp16 ----------------
__global__ void k_convX(const float* __restrict__ x, __half* __restrict__ xa) {
    int i = blockIdx.x * 256 + threadIdx.x;   // float4 index
    if (i < NN * 32) {
        float4 v = ((const float4*)x)[i];
        uint2 o;
        *(__half2*)&o.x = __floats2half2_rn(v.x, v.y);
        *(__half2*)&o.y = __floats2half2_rn(v.z, v.w);
        ((uint2*)xa)[i] = o;
    }
}

// ---------------- HMMA GEMM: Ch[nrows x 128] = fp16(A @ W), fp16 inputs, fp32 accum ----------------
// CTA = 128 rows, full K=128, 1 pass. smem 69.6 KB -> 2 CTAs/SM. Warps 4m x 2n (32x64 tiles).
#define PITCH 136
#define TILE_HW (128 * PITCH)
#define SM_A 0
#define SM_W (TILE_HW)
#define SM_GEMM_BYTES (2 * TILE_HW * 2)   // 69632

__global__ __launch_bounds__(256, 2) void k_gemm_mma(
    const __half* __restrict__ A, const __half* __restrict__ W16,
    __half* __restrict__ Ch, int nrows)
{
    extern __shared__ __half smem[];
    uint32_t sb = smem_u32(smem);
    int tid = threadIdx.x;
    int wid = tid >> 5, lane = tid & 31;
    int gblk = blockIdx.x * 128;

    // ---- fill A and W tiles via cp.async: thread -> row tid>>1, half (tid&1)*64 ----
    {
        int r  = tid >> 1;
        int kh = (tid & 1) * 64;
        uint32_t sa = sb + (uint32_t)((r * PITCH + kh) * 2);
        const __half* ga = A + (size_t)(gblk + r) * 128 + kh;
        const __half* gw = W16 + (size_t)r * 128 + kh;
        bool valid = (gblk + r < nrows);
        #pragma unroll
        for (int c = 0; c < 8; c++) {
            if (valid) cp_async16(sa + c * 16, ga + c * 8);
            cp_async16(sa + SM_W * 2 + c * 16, gw + c * 8);
        }
    }
    CP_COMMIT();
    CP_WAIT0();
    __syncthreads();

    int warp_m = wid & 3;      // rows warp_m*32
    int warp_n = wid >> 2;     // cols warp_n*64
    float acc[2][8][4];
    #pragma unroll
    for (int mi = 0; mi < 2; mi++)
        #pragma unroll
        for (int ni = 0; ni < 8; ni++)
            #pragma unroll
            for (int j = 0; j < 4; j++) acc[mi][ni][j] = 0.f;

    int lrow = lane & 15;
    int lkof = (lane >> 4) * 8;
    uint32_t aAddr = sb + (uint32_t)((SM_A + (warp_m * 32 + lrow) * PITCH + lkof) * 2);
    uint32_t bAddr = sb + (uint32_t)((SM_W + (warp_n * 64 + lrow) * PITCH + lkof) * 2);

    #pragma unroll
    for (int ks = 0; ks < 8; ks++) {
        uint32_t a0[4], a1[4];
        ldsm_x4(a0, aAddr + (uint32_t)(ks * 16) * 2);
        ldsm_x4(a1, aAddr + (uint32_t)(16 * PITCH + ks * 16) * 2);
        uint32_t b[4][4];
        #pragma unroll
        for (int nb = 0; nb < 4; nb++)
            ldsm_x4(b[nb], bAddr + (uint32_t)(nb * 16 * PITCH + ks * 16) * 2);
        #pragma unroll
        for (int nb = 0; nb < 4; nb++) {
            mma16816h(acc[0][2 * nb],     a0, b[nb][0], b[nb][2]);
            mma16816h(acc[0][2 * nb + 1], a0, b[nb][1], b[nb][3]);
            mma16816h(acc[1][2 * nb],     a1, b[nb][0], b[nb][2]);
            mma16816h(acc[1][2 * nb + 1], a1, b[nb][1], b[nb][3]);
        }
    }

    // ---- epilogue: write fp16 messages ----
    int qrow = lane >> 2;
    int qcol = (lane & 3) * 2;
    #pragma unroll
    for (int mi = 0; mi < 2; mi++) {
        int r0 = gblk + warp_m * 32 + mi * 16 + qrow;
        #pragma unroll
        for (int half = 0; half < 2; half++) {
            int gr = r0 + half * 8;
            if (gr < nrows) {
                __half* crow = Ch + (size_t)gr * 128 + warp_n * 64 + qcol;
                #pragma unroll
                for (int ni = 0; ni < 8; ni++) {
                    if (half) {
                        *(__half2*)(crow + ni * 8) =
                            __floats2half2_rn(acc[mi][ni][2], acc[mi][ni][3]);
                    } else {
                        *(__half2*)(crow + ni * 8) =
                            __floats2half2_rn(acc[mi][ni][0], acc[mi][ni][1]);
                    }
                }
            }
        }
    }
}

// ---------------- fused aggregation (fp16 msgs, fp32 accum) + bias + LN + PReLU ----------------
// last==0: write fp16 activation (oact). last==1: write fp32 out.
__global__ void k_agg_ln(const __half* __restrict__ t,
                         __half* __restrict__ oact, float* __restrict__ out32, int last,
                         const int* __restrict__ rowstart, const int* __restrict__ csr,
                         const float* __restrict__ dinv,
                         const float* __restrict__ bias, const float* __restrict__ lnw,
                         const float* __restrict__ lnb, const float* __restrict__ alpha_p) {
    int w = (blockIdx.x * blockDim.x + threadIdx.x) >> 5;
    if (w >= NN) return;
    int lane = threadIdx.x & 31;
    const uint2* t2 = (const uint2*)t;
    float di = dinv[w];
    uint2 raw = t2[(size_t)w * 32 + lane];
    float2 f0 = __half22float2(*(__half2*)&raw.x);
    float2 f1 = __half22float2(*(__half2*)&raw.y);
    float s2 = di * di;
    float4 acc = make_float4(f0.x * s2, f0.y * s2, f1.x * s2, f1.y * s2);
    int e = rowstart[w], e1 = rowstart[w + 1];
    for (; e + 1 < e1; e += 2) {
        int sA = csr[e], sB = csr[e + 1];
        float wA = dinv[sA] * di, wB = dinv[sB] * di;
        uint2 rA = t2[(size_t)sA * 32 + lane];
        uint2 rB = t2[(size_t)sB * 32 + lane];
        float2 a0 = __half22float2(*(__half2*)&rA.x);
        float2 a1 = __half22float2(*(__half2*)&rA.y);
        float2 b0 = __half22float2(*(__half2*)&rB.x);
        float2 b1 = __half22float2(*(__half2*)&rB.y);
        acc.x += wA * a0.x + wB * b0.x;
        acc.y += wA * a0.y + wB * b0.y;
        acc.z += wA * a1.x + wB * b1.x;
        acc.w += wA * a1.y + wB * b1.y;
    }
    if (e < e1) {
        int sA = csr[e];
        float wA = dinv[sA] * di;
        uint2 rA = t2[(size_t)sA * 32 + lane];
        float2 a0 = __half22float2(*(__half2*)&rA.x);
        float2 a1 = __half22float2(*(__half2*)&rA.y);
        acc.x += wA * a0.x; acc.y += wA * a0.y;
        acc.z += wA * a1.x; acc.w += wA * a1.y;
    }
    float4 b = ((const float4*)bias)[lane];
    acc.x += b.x; acc.y += b.y; acc.z += b.z; acc.w += b.w;
    float s = acc.x + acc.y + acc.z + acc.w;
    #pragma unroll
    for (int o = 16; o > 0; o >>= 1) s += __shfl_xor_sync(0xFFFFFFFFu, s, o);
    float mean = s * (1.f / 128.f);
    float dx = acc.x - mean, dy = acc.y - mean, dz = acc.z - mean, dw = acc.w - mean;
    float q = dx * dx + dy * dy + dz * dz + dw * dw;
    #pragma unroll
    for (int o = 16; o > 0; o >>= 1) q += __shfl_xor_sync(0xFFFFFFFFu, q, o);
    float rstd = rsqrtf(q * (1.f / 128.f) + LN_EPS);
    float4 gw = ((const float4*)lnw)[lane];
    float4 gb = ((const float4*)lnb)[lane];
    float a = alpha_p[0];
    float4 y;
    y.x = dx * rstd * gw.x + gb.x; y.x = y.x >= 0.f ? y.x : a * y.x;
    y.y = dy * rstd * gw.y + gb.y; y.y = y.y >= 0.f ? y.y : a * y.y;
    y.z = dz * rstd * gw.z + gb.z; y.z = y.z >= 0.f ? y.z : a * y.z;
    y.w = dw * rstd * gw.w + gb.w; y.w = y.w >= 0.f ? y.w : a * y.w;
    if (last) {
        ((float4*)out32)[(size_t)w * 32 + lane] = y;
    } else {
        uint2 o;
        *(__half2*)&o.x = __floats2half2_rn(y.x, y.y);
        *(__half2*)&o.y = __floats2half2_rn(y.z, y.w);
        ((uint2*)oact)[(size_t)w * 32 + lane] = o;
    }
}

// ---------------- launch ----------------
extern "C" void kernel_launch(void* const* d_in, const int* in_sizes, int n_in,
                              void* d_out, int out_size) {
    const float* x      = (const float*)d_in[0];
    const int*   ei     = (const int*)d_in[1];
    const float* Ws     = (const float*)d_in[2];
    const float* bs     = (const float*)d_in[3];
    const float* lnw    = (const float*)d_in[4];
    const float* lnb    = (const float*)d_in[5];
    const float* alphas = (const float*)d_in[6];
    float* out = (float*)d_out;
    const int* src = ei;
    const int* dst = ei + EE;

    float* dinv;
    __half *act, *bufh, *w16;
    int *deg, *rowstart, *cursor, *csr, *partial, *blocksums;
    cudaGetSymbolAddress((void**)&act, g_act);
    cudaGetSymbolAddress((void**)&bufh, g_bufh);
    cudaGetSymbolAddress((void**)&deg, g_deg);
    cudaGetSymbolAddress((void**)&dinv, g_dinv);
    cudaGetSymbolAddress((void**)&rowstart, g_rowstart);
    cudaGetSymbolAddress((void**)&cursor, g_cursor);
    cudaGetSymbolAddress((void**)&csr, g_csr);
    cudaGetSymbolAddress((void**)&partial, g_partial);
    cudaGetSymbolAddress((void**)&blocksums, g_blocksums);
    cudaGetSymbolAddress((void**)&w16, g_w16);

    cudaFuncSetAttribute(k_gemm_mma, cudaFuncAttributeMaxDynamicSharedMemorySize, SM_GEMM_BYTES);

    const int nbN   = (NN + 255) / 256;
    const int nbE   = (EE + 255) / 256;
    const int nbSc  = (NN + 1023) / 1024;
    const int nbRow = (NN * 32 + 255) / 256;
    const int nbG   = (NN + 127) / 128;      // 391

    // gemm layer0 at launch slot 4 (ncu profiles that slot)
    k_init_deg<<<nbN, 256>>>(deg);                                        // 1
    k_convW<<<(3 * DD * DD + 255) / 256, 256>>>(Ws, w16);                 // 2
    k_convX<<<(NN * 32 + 255) / 256, 256>>>(x, act);                      // 3
    k_gemm_mma<<<nbG, 256, SM_GEMM_BYTES>>>(act, w16, bufh, NN);          // 4 (layer 0 GEMM)
    k_hist<<<nbE, 256>>>(dst, deg);                                       // 5
    k_scan_blocks<<<nbSc, 1024>>>(deg, partial, blocksums);               // 6
    k_scan_sums<<<1, 64>>>(blocksums, nbSc);                              // 7
    k_finalize<<<nbN, 256>>>(partial, blocksums, deg, rowstart, cursor, dinv); // 8
    k_fill<<<nbE, 256>>>(src, dst, rowstart, cursor, csr);                // 9

    // layer 0 aggregation -> fp16 activations
    k_agg_ln<<<nbRow, 256>>>(bufh, act, nullptr, 0, rowstart, csr, dinv,
                             bs + 0 * DD, lnw + 0 * DD, lnb + 0 * DD, alphas + 0);
    // layer 1
    k_gemm_mma<<<nbG, 256, SM_GEMM_BYTES>>>(act, w16 + 1 * DD * DD, bufh, NN);
    k_agg_ln<<<nbRow, 256>>>(bufh, act, nullptr, 0, rowstart, csr, dinv,
                             bs + 1 * DD, lnw + 1 * DD, lnb + 1 * DD, alphas + 1);
    // layer 2 (final output fp32)
    k_gemm_mma<<<nbG, 256, SM_GEMM_BYTES>>>(act, w16 + 2 * DD * DD, bufh, NN);
    k_agg_ln<<<nbRow, 256>>>(bufh, nullptr, out, 1, rowstart, csr, dinv,
                             bs + 2 * DD, lnw + 2 * DD, lnb + 2 * DD, alphas + 2);
}